// round 1
// baseline (speedup 1.0000x reference)
#include <cuda_runtime.h>
#include <cstdint>

// Problem dims
#define SS 512
#define BB 64
#define II 1024
#define HH 1024
#define GG 3072  // 3*H

// ---------------- global scratch (static device arrays; no allocations) ----
__device__ float g_gi[(size_t)SS * BB * GG];   // precomputed input projections
__device__ float g_h[2][BB * HH];              // double-buffered hidden state
__device__ unsigned g_bar_count;
__device__ unsigned g_bar_gen;

// ---------------- helpers ----------------
__device__ __forceinline__ unsigned f2tf(float f) {
  unsigned u;
  asm("cvt.rna.tf32.f32 %0, %1;" : "=r"(u) : "f"(f));
  return u;
}

__device__ __forceinline__ void mma8(float* c,
                                     unsigned a0, unsigned a1, unsigned a2, unsigned a3,
                                     unsigned b0, unsigned b1) {
  asm volatile(
      "mma.sync.aligned.m16n8k8.row.col.f32.tf32.tf32.f32 "
      "{%0,%1,%2,%3},{%4,%5,%6,%7},{%8,%9},{%0,%1,%2,%3};"
      : "+f"(c[0]), "+f"(c[1]), "+f"(c[2]), "+f"(c[3])
      : "r"(a0), "r"(a1), "r"(a2), "r"(a3), "r"(b0), "r"(b1));
}

// =================== Phase 1: gi = x @ W_ih^T + b_ih ======================
// A = x (M=S*B x K, row-major), B = W_ih (N x K row-major) -> C = A @ B^T
#define BM 128
#define BN 128
#define BKK 16
#define APAD 20  // floats per row in smem (float4-aligned, conflict-free)

__global__ __launch_bounds__(256, 2) void gemm_gi_kernel(
    const float* __restrict__ x, const float* __restrict__ Wih,
    const float* __restrict__ bih) {
  __shared__ unsigned sA[BM * APAD];
  __shared__ unsigned sB[BN * APAD];
  const int tid = threadIdx.x;
  const int m0 = blockIdx.y * BM;
  const int n0 = blockIdx.x * BN;
  const int w = tid >> 5, lane = tid & 31;
  const int g = lane >> 2, t = lane & 3;
  const int wm = (w & 3) * 32;        // warp M offset (4 warps over M)
  const int wn = (w >> 2) * 64;       // warp N offset (2 warps over N)

  const int lr = tid >> 2;            // 0..63  (loader row, +64 on 2nd iter)
  const int lc = (tid & 3) * 4;       // 0,4,8,12 (loader col, floats)

  float acc[2][8][4];
#pragma unroll
  for (int mt = 0; mt < 2; mt++)
#pragma unroll
    for (int nt = 0; nt < 8; nt++)
#pragma unroll
      for (int i = 0; i < 4; i++) acc[mt][nt][i] = 0.f;

  float4 pA[2], pB[2];
  // preload tile k0=0
#pragma unroll
  for (int it = 0; it < 2; it++) {
    pA[it] = *(const float4*)(x + (size_t)(m0 + lr + it * 64) * II + lc);
    pB[it] = *(const float4*)(Wih + (size_t)(n0 + lr + it * 64) * II + lc);
  }
#pragma unroll
  for (int it = 0; it < 2; it++) {
    unsigned* dA = &sA[(lr + it * 64) * APAD + lc];
    dA[0] = f2tf(pA[it].x); dA[1] = f2tf(pA[it].y);
    dA[2] = f2tf(pA[it].z); dA[3] = f2tf(pA[it].w);
    unsigned* dB = &sB[(lr + it * 64) * APAD + lc];
    dB[0] = f2tf(pB[it].x); dB[1] = f2tf(pB[it].y);
    dB[2] = f2tf(pB[it].z); dB[3] = f2tf(pB[it].w);
  }
  __syncthreads();

  for (int k0 = 0; k0 < II; k0 += BKK) {
    const bool more = (k0 + BKK) < II;
    if (more) {
#pragma unroll
      for (int it = 0; it < 2; it++) {
        pA[it] = *(const float4*)(x + (size_t)(m0 + lr + it * 64) * II + k0 + BKK + lc);
        pB[it] = *(const float4*)(Wih + (size_t)(n0 + lr + it * 64) * II + k0 + BKK + lc);
      }
    }
#pragma unroll
    for (int kk = 0; kk < BKK; kk += 8) {
      unsigned a[2][4], b[8][2];
#pragma unroll
      for (int mt = 0; mt < 2; mt++) {
        const int rr = wm + mt * 16;
        a[mt][0] = sA[(rr + g) * APAD + kk + t];
        a[mt][1] = sA[(rr + 8 + g) * APAD + kk + t];
        a[mt][2] = sA[(rr + g) * APAD + kk + t + 4];
        a[mt][3] = sA[(rr + 8 + g) * APAD + kk + t + 4];
      }
#pragma unroll
      for (int nt = 0; nt < 8; nt++) {
        const int cc = wn + nt * 8 + g;
        b[nt][0] = sB[cc * APAD + kk + t];
        b[nt][1] = sB[cc * APAD + kk + t + 4];
      }
#pragma unroll
      for (int mt = 0; mt < 2; mt++)
#pragma unroll
        for (int nt = 0; nt < 8; nt++)
          mma8(acc[mt][nt], a[mt][0], a[mt][1], a[mt][2], a[mt][3],
               b[nt][0], b[nt][1]);
    }
    __syncthreads();
    if (more) {
#pragma unroll
      for (int it = 0; it < 2; it++) {
        unsigned* dA = &sA[(lr + it * 64) * APAD + lc];
        dA[0] = f2tf(pA[it].x); dA[1] = f2tf(pA[it].y);
        dA[2] = f2tf(pA[it].z); dA[3] = f2tf(pA[it].w);
        unsigned* dB = &sB[(lr + it * 64) * APAD + lc];
        dB[0] = f2tf(pB[it].x); dB[1] = f2tf(pB[it].y);
        dB[2] = f2tf(pB[it].z); dB[3] = f2tf(pB[it].w);
      }
    }
    __syncthreads();
  }

  // epilogue: += bias, write to g_gi
#pragma unroll
  for (int mt = 0; mt < 2; mt++) {
#pragma unroll
    for (int nt = 0; nt < 8; nt++) {
      const int row = m0 + wm + mt * 16 + g;
      const int col = n0 + wn + nt * 8 + 2 * t;
      const float b0v = bih[col], b1v = bih[col + 1];
      float* o = g_gi + (size_t)row * GG + col;
      o[0] = acc[mt][nt][0] + b0v;
      o[1] = acc[mt][nt][1] + b1v;
      o = g_gi + (size_t)(row + 8) * GG + col;
      o[0] = acc[mt][nt][2] + b0v;
      o[1] = acc[mt][nt][3] + b1v;
    }
  }
}

// =================== Phase 2: persistent recurrent kernel =================
#define NCTA 128
#define UPC 8          // hidden units per CTA (128*8 = 1024)
#define NC 24          // gate columns per CTA (3 gates * 8 units)
#define WPAD 1028      // smem row stride for W slice (conflict-free, f4-aligned)
#define HPAD 36        // smem row stride for h chunk
#define BKC 32         // K-chunk

__device__ __forceinline__ void grid_barrier() {
  __syncthreads();
  if (threadIdx.x == 0) {
    __threadfence();
    volatile unsigned* genp = &g_bar_gen;
    const unsigned old = *genp;
    const unsigned a = atomicAdd(&g_bar_count, 1u);
    if (a == NCTA - 1) {
      g_bar_count = 0;
      __threadfence();
      atomicExch(&g_bar_gen, old + 1u);
    } else {
      while (*genp == old) { __nanosleep(32); }
    }
    __threadfence();
  }
  __syncthreads();
}

__global__ __launch_bounds__(256, 1) void gru_rec_kernel(
    const float* __restrict__ Whh, const float* __restrict__ bhh,
    const float* __restrict__ h0, float* __restrict__ out) {
  extern __shared__ unsigned sm[];
  unsigned* sW = sm;                          // [NC][WPAD] tf32 bits
  unsigned* sH = sW + NC * WPAD;              // [64][HPAD] tf32 bits
  float* sGh = (float*)(sH + BB * HPAD);      // [2 khalf][64][NC]
  float* sBias = sGh + 2 * BB * NC;           // [NC]

  const int tid = threadIdx.x;
  const int cta = blockIdx.x;
  const int u0 = cta * UPC;

  // Preload this CTA's W_hh slice (rows: gate*H + u0+ul), converted to tf32.
  for (int i = tid; i < NC * (II / 4); i += 256) {
    const int rowl = i / (II / 4);
    const int c4 = (i % (II / 4)) * 4;
    const int gate = rowl / UPC, ul = rowl % UPC;
    const float4 v = *(const float4*)(Whh + (size_t)(gate * HH + u0 + ul) * HH + c4);
    unsigned* d = &sW[rowl * WPAD + c4];
    d[0] = f2tf(v.x); d[1] = f2tf(v.y); d[2] = f2tf(v.z); d[3] = f2tf(v.w);
  }
  if (tid < NC) {
    const int gate = tid / UPC, ul = tid % UPC;
    sBias[tid] = bhh[gate * HH + u0 + ul];
  }
  // copy init_state into h buffer 0 (each CTA its contiguous 512-float slice)
  {
    const int base = cta * 512;
    g_h[0][base + tid] = h0[base + tid];
    g_h[0][base + 256 + tid] = h0[base + 256 + tid];
  }
  grid_barrier();

  const int w = tid >> 5, lane = tid & 31;
  const int g = lane >> 2, t = lane & 3;
  const int mt = (w & 3);   // M-tile (16 batch rows)
  const int kh = (w >> 2);  // K-half

  for (int s = 0; s < SS; s++) {
    const float* cur = g_h[s & 1];
    float* nxt = g_h[(s + 1) & 1];

    float acc[3][4];
#pragma unroll
    for (int nt = 0; nt < 3; nt++)
#pragma unroll
      for (int i = 0; i < 4; i++) acc[nt][i] = 0.f;

    // load chunk 0
#pragma unroll
    for (int it = 0; it < 2; it++) {
      const int idx = tid + it * 256;
      const int r = idx >> 3, c = (idx & 7) * 4;
      const float4 v = *(const float4*)(cur + r * HH + c);
      unsigned* d = &sH[r * HPAD + c];
      d[0] = f2tf(v.x); d[1] = f2tf(v.y); d[2] = f2tf(v.z); d[3] = f2tf(v.w);
    }
    __syncthreads();

    for (int kc = 0; kc < II / BKC; kc++) {
      float4 p[2];
      const bool more = (kc + 1) < (II / BKC);
      if (more) {
#pragma unroll
        for (int it = 0; it < 2; it++) {
          const int idx = tid + it * 256;
          const int r = idx >> 3, c = (idx & 7) * 4;
          p[it] = *(const float4*)(cur + r * HH + (kc + 1) * BKC + c);
        }
      }
#pragma unroll
      for (int ks = 0; ks < 2; ks++) {
        const int kk = (kh * 2 + ks) * 8;
        const int rb = mt * 16;
        const unsigned a0 = sH[(rb + g) * HPAD + kk + t];
        const unsigned a1 = sH[(rb + 8 + g) * HPAD + kk + t];
        const unsigned a2 = sH[(rb + g) * HPAD + kk + t + 4];
        const unsigned a3 = sH[(rb + 8 + g) * HPAD + kk + t + 4];
        const int kg = kc * BKC + kk;
#pragma unroll
        for (int nt = 0; nt < 3; nt++) {
          const unsigned b0 = sW[(nt * 8 + g) * WPAD + kg + t];
          const unsigned b1 = sW[(nt * 8 + g) * WPAD + kg + t + 4];
          mma8(acc[nt], a0, a1, a2, a3, b0, b1);
        }
      }
      __syncthreads();
      if (more) {
#pragma unroll
        for (int it = 0; it < 2; it++) {
          const int idx = tid + it * 256;
          const int r = idx >> 3, c = (idx & 7) * 4;
          unsigned* d = &sH[r * HPAD + c];
          d[0] = f2tf(p[it].x); d[1] = f2tf(p[it].y);
          d[2] = f2tf(p[it].z); d[3] = f2tf(p[it].w);
        }
      }
      __syncthreads();
    }

    // write K-half partial sums of gh to smem
#pragma unroll
    for (int nt = 0; nt < 3; nt++) {
      const int col = nt * 8 + 2 * t;
      float* dst = &sGh[(kh * BB + mt * 16 + g) * NC + col];
      dst[0] = acc[nt][0];
      dst[1] = acc[nt][1];
      dst = &sGh[(kh * BB + mt * 16 + 8 + g) * NC + col];
      dst[0] = acc[nt][2];
      dst[1] = acc[nt][3];
    }
    __syncthreads();

    // pointwise GRU cell for this CTA's 8 units x 64 batch
#pragma unroll
    for (int it = 0; it < 2; it++) {
      const int idx = tid + it * 256;
      const int b = idx >> 3, ul = idx & 7;
      const int u = u0 + ul;
      const float* gi = g_gi + ((size_t)s * BB + b) * GG;
      const float ir = gi[u];
      const float iz = gi[HH + u];
      const float in_ = gi[2 * HH + u];
      const float hr = sGh[b * NC + ul] + sGh[(BB + b) * NC + ul] + sBias[ul];
      const float hz = sGh[b * NC + 8 + ul] + sGh[(BB + b) * NC + 8 + ul] + sBias[8 + ul];
      const float hn = sGh[b * NC + 16 + ul] + sGh[(BB + b) * NC + 16 + ul] + sBias[16 + ul];
      const float hp = cur[b * HH + u];
      const float r = 1.f / (1.f + __expf(-(ir + hr)));
      const float z = 1.f / (1.f + __expf(-(iz + hz)));
      const float n = tanhf(in_ + r * hn);
      const float hnew = n + z * (hp - n);
      nxt[b * HH + u] = hnew;
      out[((size_t)s * BB + b) * HH + u] = hnew;
      if (s == SS - 1) out[(size_t)SS * BB * HH + (size_t)b * HH + u] = hnew;
    }
    grid_barrier();
  }
}

// =================== launch =================
extern "C" void kernel_launch(void* const* d_in, const int* in_sizes, int n_in,
                              void* d_out, int out_size) {
  const float* x   = (const float*)d_in[0];
  const float* h0  = (const float*)d_in[1];
  const float* wih = (const float*)d_in[2];
  const float* whh = (const float*)d_in[3];
  const float* bih = (const float*)d_in[4];
  const float* bhh = (const float*)d_in[5];
  float* out = (float*)d_out;

  const int smem_rec = (NC * WPAD + BB * HPAD + 2 * BB * NC + NC) * 4;  // 120288 B
  cudaFuncSetAttribute(gru_rec_kernel, cudaFuncAttributeMaxDynamicSharedMemorySize, smem_rec);

  gemm_gi_kernel<<<dim3(GG / BN, (SS * BB) / BM), 256>>>(x, wih, bih);
  gru_rec_kernel<<<NCTA, 256, smem_rec>>>(whh, bhh, h0, out);
}

// round 3
// speedup vs baseline: 1.3016x; 1.3016x over previous
#include <cuda_runtime.h>
#include <cstdint>

// Problem dims
#define SS 512
#define BB 64
#define II 1024
#define HH 1024
#define GG 3072  // 3*H

// ---------------- global scratch ----------------
__device__ float g_gi[(size_t)SS * BB * GG];   // input projections
__device__ unsigned g_htf[2][BB * HH];         // hidden state, tf32 bits, K-pair-permuted cols
__device__ unsigned g_bar_count;
__device__ unsigned g_bar_gen;

// ---------------- helpers ----------------
__device__ __forceinline__ unsigned f2tf(float f) {
  unsigned u;
  asm("cvt.rna.tf32.f32 %0, %1;" : "=r"(u) : "f"(f));
  return u;
}

__device__ __forceinline__ void mma8(float* c,
                                     unsigned a0, unsigned a1, unsigned a2, unsigned a3,
                                     unsigned b0, unsigned b1) {
  asm volatile(
      "mma.sync.aligned.m16n8k8.row.col.f32.tf32.tf32.f32 "
      "{%0,%1,%2,%3},{%4,%5,%6,%7},{%8,%9},{%0,%1,%2,%3};"
      : "+f"(c[0]), "+f"(c[1]), "+f"(c[2]), "+f"(c[3])
      : "r"(a0), "r"(a1), "r"(a2), "r"(a3), "r"(b0), "r"(b1));
}

__device__ __forceinline__ void cp16(void* dst_smem, const void* src) {
  unsigned d = (unsigned)__cvta_generic_to_shared(dst_smem);
  asm volatile("cp.async.cg.shared.global [%0], [%1], 16;" :: "r"(d), "l"(src));
}
__device__ __forceinline__ void cp_commit() {
  asm volatile("cp.async.commit_group;");
}
template <int N>
__device__ __forceinline__ void cp_wait() {
  asm volatile("cp.async.wait_group %0;" :: "n"(N));
}

// col-within-8-block permutation: actual col j -> stored position
__device__ __forceinline__ int kperm(int j) { return ((j & 3) * 2) + (j >> 2); }

// =================== Phase 1: gi = x @ W_ih^T + b_ih ======================
#define BM 128
#define BN 128
#define BKK 16
#define APAD 20  // words per smem row (even => 8B-aligned uint2 loads)

__global__ __launch_bounds__(256, 2) void gemm_gi_kernel(
    const float* __restrict__ x, const float* __restrict__ Wih,
    const float* __restrict__ bih) {
  __shared__ unsigned sA[BM * APAD];
  __shared__ unsigned sB[BN * APAD];
  const int tid = threadIdx.x;
  const int m0 = blockIdx.y * BM;
  const int n0 = blockIdx.x * BN;
  const int w = tid >> 5, lane = tid & 31;
  const int g = lane >> 2, t = lane & 3;
  const int wm = (w & 3) * 32;
  const int wn = (w >> 2) * 64;

  const int lr = tid >> 2;
  const int lc = (tid & 3) * 4;                       // 0,4,8,12
  const int loff = ((lc >> 3) * 8) + ((lc & 4) >> 2); // permuted base position

  float acc[2][8][4];
#pragma unroll
  for (int mt = 0; mt < 2; mt++)
#pragma unroll
    for (int nt = 0; nt < 8; nt++)
#pragma unroll
      for (int i = 0; i < 4; i++) acc[mt][nt][i] = 0.f;

  float4 pA[2], pB[2];
#pragma unroll
  for (int it = 0; it < 2; it++) {
    pA[it] = *(const float4*)(x + (size_t)(m0 + lr + it * 64) * II + lc);
    pB[it] = *(const float4*)(Wih + (size_t)(n0 + lr + it * 64) * II + lc);
  }
#pragma unroll
  for (int it = 0; it < 2; it++) {
    unsigned* dA = &sA[(lr + it * 64) * APAD + loff];
    dA[0] = f2tf(pA[it].x); dA[2] = f2tf(pA[it].y);
    dA[4] = f2tf(pA[it].z); dA[6] = f2tf(pA[it].w);
    unsigned* dB = &sB[(lr + it * 64) * APAD + loff];
    dB[0] = f2tf(pB[it].x); dB[2] = f2tf(pB[it].y);
    dB[4] = f2tf(pB[it].z); dB[6] = f2tf(pB[it].w);
  }
  __syncthreads();

  for (int k0 = 0; k0 < II; k0 += BKK) {
    const bool more = (k0 + BKK) < II;
    if (more) {
#pragma unroll
      for (int it = 0; it < 2; it++) {
        pA[it] = *(const float4*)(x + (size_t)(m0 + lr + it * 64) * II + k0 + BKK + lc);
        pB[it] = *(const float4*)(Wih + (size_t)(n0 + lr + it * 64) * II + k0 + BKK + lc);
      }
    }
#pragma unroll
    for (int kk8 = 0; kk8 < 2; kk8++) {
      uint2 a[2][2];
#pragma unroll
      for (int mt = 0; mt < 2; mt++) {
        const unsigned* ap = &sA[(wm + mt * 16 + g) * APAD + kk8 * 8 + 2 * t];
        a[mt][0] = *(const uint2*)ap;              // a0 (row g, t), a2 (row g, t+4)
        a[mt][1] = *(const uint2*)(ap + 8 * APAD); // a1, a3 (row g+8)
      }
#pragma unroll
      for (int nt = 0; nt < 8; nt++) {
        const uint2 b = *(const uint2*)&sB[(wn + nt * 8 + g) * APAD + kk8 * 8 + 2 * t];
#pragma unroll
        for (int mt = 0; mt < 2; mt++)
          mma8(acc[mt][nt], a[mt][0].x, a[mt][1].x, a[mt][0].y, a[mt][1].y, b.x, b.y);
      }
    }
    __syncthreads();
    if (more) {
#pragma unroll
      for (int it = 0; it < 2; it++) {
        unsigned* dA = &sA[(lr + it * 64) * APAD + loff];
        dA[0] = f2tf(pA[it].x); dA[2] = f2tf(pA[it].y);
        dA[4] = f2tf(pA[it].z); dA[6] = f2tf(pA[it].w);
        unsigned* dB = &sB[(lr + it * 64) * APAD + loff];
        dB[0] = f2tf(pB[it].x); dB[2] = f2tf(pB[it].y);
        dB[4] = f2tf(pB[it].z); dB[6] = f2tf(pB[it].w);
      }
    }
    __syncthreads();
  }

#pragma unroll
  for (int mt = 0; mt < 2; mt++) {
#pragma unroll
    for (int nt = 0; nt < 8; nt++) {
      const int row = m0 + wm + mt * 16 + g;
      const int col = n0 + wn + nt * 8 + 2 * t;
      const float b0v = bih[col], b1v = bih[col + 1];
      float* o = g_gi + (size_t)row * GG + col;
      o[0] = acc[mt][nt][0] + b0v;
      o[1] = acc[mt][nt][1] + b1v;
      o = g_gi + (size_t)(row + 8) * GG + col;
      o[0] = acc[mt][nt][2] + b0v;
      o[1] = acc[mt][nt][3] + b1v;
    }
  }
}

// =================== Phase 2: persistent recurrent kernel =================
#define NCTA 128
#define UPC 8
#define NC 24          // 3 gates * 8 units
#define WPAD 1032      // even, uint2-aligned
#define HPAD 132       // multiple of 4 words (16B cp.async dst align)
#define CHUNK 128      // h columns per staged chunk
#define NCHUNK (HH / CHUNK)  // 8

__device__ __forceinline__ void grid_barrier() {
  __syncthreads();
  if (threadIdx.x == 0) {
    __threadfence();
    volatile unsigned* genp = &g_bar_gen;
    const unsigned old = *genp;
    const unsigned a = atomicAdd(&g_bar_count, 1u);
    if (a == NCTA - 1) {
      g_bar_count = 0;
      __threadfence();
      atomicExch(&g_bar_gen, old + 1u);
    } else {
      while (*genp == old) { __nanosleep(32); }
    }
    __threadfence();
  }
  __syncthreads();
}

__global__ __launch_bounds__(256, 1) void gru_rec_kernel(
    const float* __restrict__ Whh, const float* __restrict__ bhh,
    const float* __restrict__ h0, float* __restrict__ out) {
  extern __shared__ unsigned sm[];
  unsigned* sW = sm;                                   // [NC][WPAD] tf32, K-pair-permuted
  unsigned* sHb[2];
  sHb[0] = sW + NC * WPAD;                             // [64][HPAD]
  sHb[1] = sHb[0] + BB * HPAD;
  float* sGh = (float*)(sHb[1] + BB * HPAD);           // [2][64][NC]
  float* sBias = sGh + 2 * BB * NC;                    // [NC]
  float* sHp = sBias + NC;                             // [512] own fp32 h slice

  const int tid = threadIdx.x;
  const int cta = blockIdx.x;
  const int u0 = cta * UPC;

  // Stage W_hh slice, tf32, K-pair-permuted
  for (int i = tid; i < NC * (II / 4); i += 256) {
    const int rowl = i / (II / 4);
    const int c4 = (i % (II / 4)) * 4;
    const int gate = rowl / UPC, ul = rowl % UPC;
    const float4 v = *(const float4*)(Whh + (size_t)(gate * HH + u0 + ul) * HH + c4);
    unsigned* d = &sW[rowl * WPAD + ((c4 >> 3) * 8) + ((c4 & 4) >> 2)];
    d[0] = f2tf(v.x); d[2] = f2tf(v.y); d[4] = f2tf(v.z); d[6] = f2tf(v.w);
  }
  if (tid < NC) {
    const int gate = tid / UPC, ul = tid % UPC;
    sBias[tid] = bhh[gate * HH + u0 + ul];
  }
  // init h0: own columns only (fp32 in smem, permuted tf32 in global)
#pragma unroll
  for (int it = 0; it < 2; it++) {
    const int idx = tid + it * 256;
    const int b = idx >> 3, j = idx & 7;
    const float v = h0[b * HH + u0 + j];
    sHp[idx] = v;
    g_htf[0][b * HH + u0 + kperm(j)] = f2tf(v);
  }
  grid_barrier();

  const int w = tid >> 5, lane = tid & 31;
  const int g = lane >> 2, t = lane & 3;
  const int mt = (w & 3);   // M tile (16 batch rows)
  const int kh = (w >> 2);  // K half within a chunk

  // per-thread cp.async indices (8 float4s per chunk)
  const int cr = tid >> 5;          // not used directly; computed in loop
  (void)cr;

  for (int s = 0; s < SS; s++) {
    const unsigned* cur = g_htf[s & 1];
    unsigned* nxt = g_htf[(s + 1) & 1];

    // issue chunks 0 and 1
#pragma unroll
    for (int c = 0; c < 2; c++) {
#pragma unroll
      for (int k = 0; k < 8; k++) {
        const int f = tid + k * 256;          // float4 index 0..2047
        const int r = f >> 5, c4 = (f & 31) * 4;
        cp16(&sHb[c][r * HPAD + c4], cur + (size_t)r * HH + c * CHUNK + c4);
      }
      cp_commit();
    }

    // prefetch gi for this step (hides DRAM latency under the stream)
    float gir[2], giz[2], gin[2];
    {
      const float* gb = g_gi + (size_t)s * BB * GG;
#pragma unroll
      for (int it = 0; it < 2; it++) {
        const int idx = tid + it * 256;
        const int b = idx >> 3, j = idx & 7;
        const float* p = gb + (size_t)b * GG + u0 + j;
        gir[it] = p[0];
        giz[it] = p[HH];
        gin[it] = p[2 * HH];
      }
    }

    float acc[3][4];
#pragma unroll
    for (int nt = 0; nt < 3; nt++)
#pragma unroll
      for (int i = 0; i < 4; i++) acc[nt][i] = 0.f;

    for (int kc = 0; kc < NCHUNK; kc++) {
      if (kc < NCHUNK - 1) cp_wait<1>(); else cp_wait<0>();
      __syncthreads();
      const unsigned* sh = sHb[kc & 1];
#pragma unroll
      for (int ks = 0; ks < 8; ks++) {
        const int kk8 = kh * 8 + ks;                  // k8 block within chunk (0..15)
        const unsigned* ap = &sh[(mt * 16 + g) * HPAD + kk8 * 8 + 2 * t];
        const uint2 alo = *(const uint2*)ap;           // a0,a2
        const uint2 ahi = *(const uint2*)(ap + 8 * HPAD); // a1,a3
        const int kg = (kc * 16 + kk8) * 8 + 2 * t;
#pragma unroll
        for (int nt = 0; nt < 3; nt++) {
          const uint2 b = *(const uint2*)&sW[(nt * 8 + g) * WPAD + kg];
          mma8(acc[nt], alo.x, ahi.x, alo.y, ahi.y, b.x, b.y);
        }
      }
      __syncthreads();
      if (kc + 2 < NCHUNK) {
        unsigned* buf = sHb[kc & 1];
#pragma unroll
        for (int k = 0; k < 8; k++) {
          const int f = tid + k * 256;
          const int r = f >> 5, c4 = (f & 31) * 4;
          cp16(&buf[r * HPAD + c4], cur + (size_t)r * HH + (kc + 2) * CHUNK + c4);
        }
        cp_commit();
      }
    }

    // write K-half partials of gh
#pragma unroll
    for (int nt = 0; nt < 3; nt++) {
      const int col = nt * 8 + 2 * t;
      float* dst = &sGh[(kh * BB + mt * 16 + g) * NC + col];
      dst[0] = acc[nt][0];
      dst[1] = acc[nt][1];
      dst = &sGh[(kh * BB + mt * 16 + 8 + g) * NC + col];
      dst[0] = acc[nt][2];
      dst[1] = acc[nt][3];
    }
    __syncthreads();

    // pointwise GRU cell: this CTA's 8 units x 64 batch
#pragma unroll
    for (int it = 0; it < 2; it++) {
      const int idx = tid + it * 256;
      const int b = idx >> 3, j = idx & 7;
      const int u = u0 + j;
      const float hr = sGh[b * NC + j] + sGh[(BB + b) * NC + j] + sBias[j];
      const float hz = sGh[b * NC + 8 + j] + sGh[(BB + b) * NC + 8 + j] + sBias[8 + j];
      const float hn = sGh[b * NC + 16 + j] + sGh[(BB + b) * NC + 16 + j] + sBias[16 + j];
      const float hp = sHp[idx];
      const float r = 1.f / (1.f + __expf(-(gir[it] + hr)));
      const float z = 1.f / (1.f + __expf(-(giz[it] + hz)));
      const float n = tanhf(gin[it] + r * hn);
      const float hnew = n + z * (hp - n);
      sHp[idx] = hnew;
      nxt[b * HH + u0 + kperm(j)] = f2tf(hnew);
      out[((size_t)s * BB + b) * HH + u] = hnew;
      if (s == SS - 1) out[(size_t)SS * BB * HH + (size_t)b * HH + u] = hnew;
    }
    grid_barrier();
  }
}

// =================== launch =================
extern "C" void kernel_launch(void* const* d_in, const int* in_sizes, int n_in,
                              void* d_out, int out_size) {
  const float* x   = (const float*)d_in[0];
  const float* h0  = (const float*)d_in[1];
  const float* wih = (const float*)d_in[2];
  const float* whh = (const float*)d_in[3];
  const float* bih = (const float*)d_in[4];
  const float* bhh = (const float*)d_in[5];
  float* out = (float*)d_out;

  const int smem_rec =
      (NC * WPAD + 2 * BB * HPAD + 2 * BB * NC + NC + 512) * 4;  // 181,088 B
  cudaFuncSetAttribute(gru_rec_kernel, cudaFuncAttributeMaxDynamicSharedMemorySize, smem_rec);

  gemm_gi_kernel<<<dim3(GG / BN, (SS * BB) / BM), 256>>>(x, wih, bih);
  gru_rec_kernel<<<NCTA, 256, smem_rec>>>(whh, bhh, h0, out);
}

// round 5
// speedup vs baseline: 2.0408x; 1.5679x over previous
#include <cuda_runtime.h>
#include <cuda_fp16.h>
#include <cstdint>

// Problem dims
#define SS 512
#define BB 64
#define II 1024
#define HH 1024
#define GG 3072  // 3*H

// ---------------- global scratch ----------------
__device__ float g_gi[(size_t)SS * BB * GG];     // input projections (fp32)
__device__ unsigned g_htf[2][BB * (HH / 2)];     // hidden state, half2 packed, k16-perm
__device__ unsigned g_leaf[8 * 32];              // leaf counters, 128B apart
__device__ unsigned g_root;
__device__ unsigned g_bar_gen;

// ---------------- helpers ----------------
__device__ __forceinline__ unsigned packh2(float lo, float hi) {
  __half2 h = __floats2half2_rn(lo, hi);
  return *(unsigned*)&h;
}

// half2-index permutation within each 8-half2 (k16) block:
// jh -> blockbase + (jh&3)*2 + ((jh>>2)&1)
__device__ __forceinline__ int hperm(int jh) {
  return (jh & ~7) + ((jh & 3) * 2) + ((jh >> 2) & 1);
}

__device__ __forceinline__ void mma16(float* c,
                                      unsigned a0, unsigned a1, unsigned a2, unsigned a3,
                                      unsigned b0, unsigned b1) {
  asm volatile(
      "mma.sync.aligned.m16n8k16.row.col.f32.f16.f16.f32 "
      "{%0,%1,%2,%3},{%4,%5,%6,%7},{%8,%9},{%0,%1,%2,%3};"
      : "+f"(c[0]), "+f"(c[1]), "+f"(c[2]), "+f"(c[3])
      : "r"(a0), "r"(a1), "r"(a2), "r"(a3), "r"(b0), "r"(b1));
}

__device__ __forceinline__ void cp16(void* dst_smem, const void* src) {
  unsigned d = (unsigned)__cvta_generic_to_shared(dst_smem);
  asm volatile("cp.async.cg.shared.global [%0], [%1], 16;" :: "r"(d), "l"(src));
}
__device__ __forceinline__ void cp_commit() {
  asm volatile("cp.async.commit_group;");
}
template <int N>
__device__ __forceinline__ void cp_wait() {
  asm volatile("cp.async.wait_group %0;" :: "n"(N));
}

// =================== Phase 1: gi = x @ W_ih^T + b_ih (fp16 MMA) ===========
#define BM 128
#define BN 128
#define BKK 16    // k columns per tile (one k16 block)
#define AP2 10    // half2 words per smem row (8 data + 2 pad, even)

__global__ __launch_bounds__(256, 2) void gemm_gi_kernel(
    const float* __restrict__ x, const float* __restrict__ Wih,
    const float* __restrict__ bih) {
  __shared__ unsigned sA[BM * AP2];
  __shared__ unsigned sB[BN * AP2];
  const int tid = threadIdx.x;
  const int m0 = blockIdx.y * BM;
  const int n0 = blockIdx.x * BN;
  const int w = tid >> 5, lane = tid & 31;
  const int g = lane >> 2, t = lane & 3;
  const int wm = (w & 3) * 32;
  const int wn = (w >> 2) * 64;

  const int lr = tid >> 2;
  const int lc = (tid & 3) * 4;            // float col: 0,4,8,12
  const int p0 = hperm(lc >> 1);           // permuted half2 position of (lc,lc+1)

  float acc[2][8][4];
#pragma unroll
  for (int mt = 0; mt < 2; mt++)
#pragma unroll
    for (int nt = 0; nt < 8; nt++)
#pragma unroll
      for (int i = 0; i < 4; i++) acc[mt][nt][i] = 0.f;

  float4 pA[2], pB[2];
#pragma unroll
  for (int it = 0; it < 2; it++) {
    pA[it] = *(const float4*)(x + (size_t)(m0 + lr + it * 64) * II + lc);
    pB[it] = *(const float4*)(Wih + (size_t)(n0 + lr + it * 64) * II + lc);
  }
#pragma unroll
  for (int it = 0; it < 2; it++) {
    unsigned* dA = &sA[(lr + it * 64) * AP2];
    dA[p0] = packh2(pA[it].x, pA[it].y);
    dA[p0 + 2] = packh2(pA[it].z, pA[it].w);
    unsigned* dB = &sB[(lr + it * 64) * AP2];
    dB[p0] = packh2(pB[it].x, pB[it].y);
    dB[p0 + 2] = packh2(pB[it].z, pB[it].w);
  }
  __syncthreads();

  for (int k0 = 0; k0 < II; k0 += BKK) {
    const bool more = (k0 + BKK) < II;
    if (more) {
#pragma unroll
      for (int it = 0; it < 2; it++) {
        pA[it] = *(const float4*)(x + (size_t)(m0 + lr + it * 64) * II + k0 + BKK + lc);
        pB[it] = *(const float4*)(Wih + (size_t)(n0 + lr + it * 64) * II + k0 + BKK + lc);
      }
    }
    {
      uint2 a[2][2];
#pragma unroll
      for (int mt = 0; mt < 2; mt++) {
        const unsigned* ap = &sA[(wm + mt * 16 + g) * AP2 + 2 * t];
        a[mt][0] = *(const uint2*)ap;               // a0 (k=2t..), a2 (k=2t+8..)
        a[mt][1] = *(const uint2*)(ap + 8 * AP2);   // a1, a3
      }
#pragma unroll
      for (int nt = 0; nt < 8; nt++) {
        const uint2 b = *(const uint2*)&sB[(wn + nt * 8 + g) * AP2 + 2 * t];
#pragma unroll
        for (int mt = 0; mt < 2; mt++)
          mma16(acc[mt][nt], a[mt][0].x, a[mt][1].x, a[mt][0].y, a[mt][1].y, b.x, b.y);
      }
    }
    __syncthreads();
    if (more) {
#pragma unroll
      for (int it = 0; it < 2; it++) {
        unsigned* dA = &sA[(lr + it * 64) * AP2];
        dA[p0] = packh2(pA[it].x, pA[it].y);
        dA[p0 + 2] = packh2(pA[it].z, pA[it].w);
        unsigned* dB = &sB[(lr + it * 64) * AP2];
        dB[p0] = packh2(pB[it].x, pB[it].y);
        dB[p0 + 2] = packh2(pB[it].z, pB[it].w);
      }
    }
    __syncthreads();
  }

#pragma unroll
  for (int mt = 0; mt < 2; mt++) {
#pragma unroll
    for (int nt = 0; nt < 8; nt++) {
      const int row = m0 + wm + mt * 16 + g;
      const int col = n0 + wn + nt * 8 + 2 * t;
      const float b0v = bih[col], b1v = bih[col + 1];
      float* o = g_gi + (size_t)row * GG + col;
      o[0] = acc[mt][nt][0] + b0v;
      o[1] = acc[mt][nt][1] + b1v;
      o = g_gi + (size_t)(row + 8) * GG + col;
      o[0] = acc[mt][nt][2] + b0v;
      o[1] = acc[mt][nt][3] + b1v;
    }
  }
}

// =================== Phase 2: persistent recurrent kernel =================
#define NCTA 128
#define UPC 8
#define NC 24              // 3 gates * 8 units
#define WP2 520            // half2 per W smem row (512 + pad, even)
#define HP2 68             // half2 per h-chunk smem row (64 + 4 pad; 272B = 16B mult)
#define CHUNK2 64          // half2 per chunk per row (=128 h columns)
#define NCHUNK 8

__device__ __forceinline__ void grid_barrier() {
  __syncthreads();
  if (threadIdx.x == 0) {
    __threadfence();
    volatile unsigned* genp = &g_bar_gen;
    const unsigned old = *genp;
    const int leaf = blockIdx.x >> 4;
    if (atomicAdd(&g_leaf[leaf * 32], 1u) == 15u) {
      if (atomicAdd(&g_root, 1u) == 7u) {
        g_root = 0;
#pragma unroll
        for (int i = 0; i < 8; i++) g_leaf[i * 32] = 0;
        __threadfence();
        atomicExch(&g_bar_gen, old + 1u);
      }
    }
    while (*genp == old) {}
    __threadfence();
  }
  __syncthreads();
}

__global__ __launch_bounds__(256, 1) void gru_rec_kernel(
    const float* __restrict__ Whh, const float* __restrict__ bhh,
    const float* __restrict__ h0, float* __restrict__ out) {
  extern __shared__ unsigned sm[];
  unsigned* sW = sm;                                   // [NC][WP2] half2, k16-perm
  unsigned* sHb[3];
  sHb[0] = sW + NC * WP2;                              // [64][HP2] half2
  sHb[1] = sHb[0] + BB * HP2;
  sHb[2] = sHb[1] + BB * HP2;
  float* sGh = (float*)(sHb[2] + BB * HP2);            // [2][64][NC]
  float* sBias = sGh + 2 * BB * NC;                    // [NC]
  float* sHp = sBias + NC;                             // [512] own fp32 h slice

  const int tid = threadIdx.x;
  const int cta = blockIdx.x;
  const int u0 = cta * UPC;

  // Stage W_hh slice as half2, k16-permuted.
  for (int i = tid; i < NC * (II / 4); i += 256) {
    const int rowl = i >> 8;                 // 256 float4 per row
    const int c4 = (i & 255) * 4;            // float col
    const int gate = rowl / UPC, ul = rowl % UPC;
    const float4 v = *(const float4*)(Whh + (size_t)(gate * HH + u0 + ul) * HH + c4);
    unsigned* d = &sW[rowl * WP2];
    const int p = hperm(c4 >> 1);
    d[p] = packh2(v.x, v.y);
    d[p + 2] = packh2(v.z, v.w);
  }
  if (tid < NC) {
    const int gate = tid / UPC, ul = tid % UPC;
    sBias[tid] = bhh[gate * HH + u0 + ul];
  }
  // init h0: own 8 columns (fp32 smem copy + packed permuted half2 in global)
#pragma unroll
  for (int it = 0; it < 2; it++) {
    const int idx = tid + it * 256;
    const int b = idx >> 3, j = idx & 7;
    const float v = h0[b * HH + u0 + j];
    sHp[idx] = v;
    if ((j & 1) == 0) {
      const float v1 = h0[b * HH + u0 + j + 1];
      g_htf[0][b * (HH / 2) + hperm(4 * cta + (j >> 1))] = packh2(v, v1);
    }
  }
  grid_barrier();

  const int w = tid >> 5, lane = tid & 31;
  const int g = lane >> 2, t = lane & 3;
  const int mt = (w & 3);   // M tile (16 batch rows)
  const int kh = (w >> 2);  // K half within a chunk (4 k16 blocks each)

  for (int s = 0; s < SS; s++) {
    const unsigned* cur = g_htf[s & 1];
    unsigned* nxt = g_htf[(s + 1) & 1];

    // issue chunks 0..2 (3-deep pipeline)
#pragma unroll
    for (int c = 0; c < 3; c++) {
#pragma unroll
      for (int k = 0; k < 4; k++) {
        const int f = tid + k * 256;               // float4 index 0..1023
        const int r = f >> 4, cu = (f & 15) * 4;   // row, half2 offset
        cp16(&sHb[c][r * HP2 + cu], cur + (size_t)r * (HH / 2) + c * CHUNK2 + cu);
      }
      cp_commit();
    }

    // prefetch gi for this step
    float gir[2], giz[2], gin[2];
    {
      const float* gb = g_gi + (size_t)s * BB * GG;
#pragma unroll
      for (int it = 0; it < 2; it++) {
        const int idx = tid + it * 256;
        const int b = idx >> 3, j = idx & 7;
        const float* p = gb + (size_t)b * GG + u0 + j;
        gir[it] = p[0];
        giz[it] = p[HH];
        gin[it] = p[2 * HH];
      }
    }

    float acc[3][4];
#pragma unroll
    for (int nt = 0; nt < 3; nt++)
#pragma unroll
      for (int i = 0; i < 4; i++) acc[nt][i] = 0.f;

    for (int kc = 0; kc < NCHUNK; kc++) {
      if (kc <= 5) cp_wait<2>();
      else if (kc == 6) cp_wait<1>();
      else cp_wait<0>();
      __syncthreads();
      const unsigned* sh = sHb[kc % 3];
#pragma unroll
      for (int ks = 0; ks < 4; ks++) {
        const int kk = kh * 4 + ks;                       // k16 block within chunk (0..7)
        const unsigned* ap = &sh[(mt * 16 + g) * HP2 + kk * 8 + 2 * t];
        const uint2 alo = *(const uint2*)ap;              // a0, a2
        const uint2 ahi = *(const uint2*)(ap + 8 * HP2);  // a1, a3
        const int kg = (kc * 8 + kk) * 8 + 2 * t;         // FIX: 8 k16 blocks per chunk
#pragma unroll
        for (int nt = 0; nt < 3; nt++) {
          const uint2 b = *(const uint2*)&sW[(nt * 8 + g) * WP2 + kg];
          mma16(acc[nt], alo.x, ahi.x, alo.y, ahi.y, b.x, b.y);
        }
      }
      __syncthreads();
      if (kc + 3 < NCHUNK) {
        unsigned* buf = sHb[kc % 3];
#pragma unroll
        for (int k = 0; k < 4; k++) {
          const int f = tid + k * 256;
          const int r = f >> 4, cu = (f & 15) * 4;
          cp16(&buf[r * HP2 + cu], cur + (size_t)r * (HH / 2) + (kc + 3) * CHUNK2 + cu);
        }
        cp_commit();
      }
    }

    // write K-half partials of gh
#pragma unroll
    for (int nt = 0; nt < 3; nt++) {
      const int col = nt * 8 + 2 * t;
      float* dst = &sGh[(kh * BB + mt * 16 + g) * NC + col];
      dst[0] = acc[nt][0];
      dst[1] = acc[nt][1];
      dst = &sGh[(kh * BB + mt * 16 + 8 + g) * NC + col];
      dst[0] = acc[nt][2];
      dst[1] = acc[nt][3];
    }
    __syncthreads();

    // pointwise GRU cell: this CTA's 8 units x 64 batch
#pragma unroll
    for (int it = 0; it < 2; it++) {
      const int idx = tid + it * 256;
      const int b = idx >> 3, j = idx & 7;
      const int u = u0 + j;
      const float hr = sGh[b * NC + j] + sGh[(BB + b) * NC + j] + sBias[j];
      const float hz = sGh[b * NC + 8 + j] + sGh[(BB + b) * NC + 8 + j] + sBias[8 + j];
      const float hn = sGh[b * NC + 16 + j] + sGh[(BB + b) * NC + 16 + j] + sBias[16 + j];
      const float hp = sHp[idx];
      const float r = 1.f / (1.f + __expf(-(gir[it] + hr)));
      const float z = 1.f / (1.f + __expf(-(giz[it] + hz)));
      const float n = tanhf(gin[it] + r * hn);
      const float hnew = n + z * (hp - n);
      sHp[idx] = hnew;
      // pack pairs (j even takes j+1's value from the next lane)
      const float hi = __shfl_down_sync(0xffffffffu, hnew, 1);
      if ((j & 1) == 0)
        nxt[b * (HH / 2) + hperm(4 * cta + (j >> 1))] = packh2(hnew, hi);
      out[((size_t)s * BB + b) * HH + u] = hnew;
      if (s == SS - 1) out[(size_t)SS * BB * HH + (size_t)b * HH + u] = hnew;
    }
    grid_barrier();
  }
}

// =================== launch =================
extern "C" void kernel_launch(void* const* d_in, const int* in_sizes, int n_in,
                              void* d_out, int out_size) {
  const float* x   = (const float*)d_in[0];
  const float* h0  = (const float*)d_in[1];
  const float* wih = (const float*)d_in[2];
  const float* whh = (const float*)d_in[3];
  const float* bih = (const float*)d_in[4];
  const float* bhh = (const float*)d_in[5];
  float* out = (float*)d_out;

  const int smem_rec =
      (NC * WP2 + 3 * BB * HP2 + 2 * BB * NC + NC + 512) * 4;  // ~116.6 KB
  cudaFuncSetAttribute(gru_rec_kernel, cudaFuncAttributeMaxDynamicSharedMemorySize, smem_rec);

  gemm_gi_kernel<<<dim3(GG / BN, (SS * BB) / BM), 256>>>(x, wih, bih);
  gru_rec_kernel<<<NCTA, 256, smem_rec>>>(whh, bhh, h0, out);
}

// round 6
// speedup vs baseline: 2.3655x; 1.1591x over previous
#include <cuda_runtime.h>
#include <cuda_fp16.h>
#include <cstdint>

// Problem dims
#define SS 512
#define BB 64
#define II 1024
#define HH 1024
#define GG 3072  // 3*H

#define GRP 2        // independent batch groups
#define RPG 32       // batch rows per group
#define CPG 64       // CTAs per group
#define H2 512       // half2 words per h row

// ---------------- global scratch ----------------
__device__ float g_gi[(size_t)SS * BB * GG];       // input projections (fp32)
__device__ unsigned g_h2[GRP][2][RPG * H2];        // h, half2 packed, k16-perm, per group
__device__ unsigned g_leaf[GRP * 8 * 32];          // leaf counters, 128B apart
__device__ unsigned g_root[GRP * 32];
__device__ unsigned g_gen[GRP * 32];

// ---------------- helpers ----------------
__device__ __forceinline__ unsigned packh2(float lo, float hi) {
  __half2 h = __floats2half2_rn(lo, hi);
  return *(unsigned*)&h;
}

// half2-index permutation within each 8-half2 (k16) block
__device__ __forceinline__ int hperm(int jh) {
  return (jh & ~7) + ((jh & 3) * 2) + ((jh >> 2) & 1);
}

__device__ __forceinline__ void mma16(float* c,
                                      unsigned a0, unsigned a1, unsigned a2, unsigned a3,
                                      unsigned b0, unsigned b1) {
  asm volatile(
      "mma.sync.aligned.m16n8k16.row.col.f32.f16.f16.f32 "
      "{%0,%1,%2,%3},{%4,%5,%6,%7},{%8,%9},{%0,%1,%2,%3};"
      : "+f"(c[0]), "+f"(c[1]), "+f"(c[2]), "+f"(c[3])
      : "r"(a0), "r"(a1), "r"(a2), "r"(a3), "r"(b0), "r"(b1));
}

__device__ __forceinline__ void cp16(void* dst_smem, const void* src) {
  unsigned d = (unsigned)__cvta_generic_to_shared(dst_smem);
  asm volatile("cp.async.cg.shared.global [%0], [%1], 16;" :: "r"(d), "l"(src));
}
__device__ __forceinline__ void cp_commit() {
  asm volatile("cp.async.commit_group;");
}
template <int N>
__device__ __forceinline__ void cp_wait() {
  asm volatile("cp.async.wait_group %0;" :: "n"(N));
}

// =================== Phase 1: gi = x @ W_ih^T + b_ih (fp16 MMA) ===========
#define BM 128
#define BN 128
#define BKK 16
#define AP2 10

__global__ __launch_bounds__(256, 2) void gemm_gi_kernel(
    const float* __restrict__ x, const float* __restrict__ Wih,
    const float* __restrict__ bih) {
  __shared__ unsigned sA[BM * AP2];
  __shared__ unsigned sB[BN * AP2];
  const int tid = threadIdx.x;
  const int m0 = blockIdx.y * BM;
  const int n0 = blockIdx.x * BN;
  const int w = tid >> 5, lane = tid & 31;
  const int gq = lane >> 2, t = lane & 3;
  const int wm = (w & 3) * 32;
  const int wn = (w >> 2) * 64;

  const int lr = tid >> 2;
  const int lc = (tid & 3) * 4;
  const int p0 = hperm(lc >> 1);

  float acc[2][8][4];
#pragma unroll
  for (int mt = 0; mt < 2; mt++)
#pragma unroll
    for (int nt = 0; nt < 8; nt++)
#pragma unroll
      for (int i = 0; i < 4; i++) acc[mt][nt][i] = 0.f;

  float4 pA[2], pB[2];
#pragma unroll
  for (int it = 0; it < 2; it++) {
    pA[it] = *(const float4*)(x + (size_t)(m0 + lr + it * 64) * II + lc);
    pB[it] = *(const float4*)(Wih + (size_t)(n0 + lr + it * 64) * II + lc);
  }
#pragma unroll
  for (int it = 0; it < 2; it++) {
    unsigned* dA = &sA[(lr + it * 64) * AP2];
    dA[p0] = packh2(pA[it].x, pA[it].y);
    dA[p0 + 2] = packh2(pA[it].z, pA[it].w);
    unsigned* dB = &sB[(lr + it * 64) * AP2];
    dB[p0] = packh2(pB[it].x, pB[it].y);
    dB[p0 + 2] = packh2(pB[it].z, pB[it].w);
  }
  __syncthreads();

  for (int k0 = 0; k0 < II; k0 += BKK) {
    const bool more = (k0 + BKK) < II;
    if (more) {
#pragma unroll
      for (int it = 0; it < 2; it++) {
        pA[it] = *(const float4*)(x + (size_t)(m0 + lr + it * 64) * II + k0 + BKK + lc);
        pB[it] = *(const float4*)(Wih + (size_t)(n0 + lr + it * 64) * II + k0 + BKK + lc);
      }
    }
    {
      uint2 a[2][2];
#pragma unroll
      for (int mt = 0; mt < 2; mt++) {
        const unsigned* ap = &sA[(wm + mt * 16 + gq) * AP2 + 2 * t];
        a[mt][0] = *(const uint2*)ap;
        a[mt][1] = *(const uint2*)(ap + 8 * AP2);
      }
#pragma unroll
      for (int nt = 0; nt < 8; nt++) {
        const uint2 b = *(const uint2*)&sB[(wn + nt * 8 + gq) * AP2 + 2 * t];
#pragma unroll
        for (int mt = 0; mt < 2; mt++)
          mma16(acc[mt][nt], a[mt][0].x, a[mt][1].x, a[mt][0].y, a[mt][1].y, b.x, b.y);
      }
    }
    __syncthreads();
    if (more) {
#pragma unroll
      for (int it = 0; it < 2; it++) {
        unsigned* dA = &sA[(lr + it * 64) * AP2];
        dA[p0] = packh2(pA[it].x, pA[it].y);
        dA[p0 + 2] = packh2(pA[it].z, pA[it].w);
        unsigned* dB = &sB[(lr + it * 64) * AP2];
        dB[p0] = packh2(pB[it].x, pB[it].y);
        dB[p0 + 2] = packh2(pB[it].z, pB[it].w);
      }
    }
    __syncthreads();
  }

#pragma unroll
  for (int mt = 0; mt < 2; mt++) {
#pragma unroll
    for (int nt = 0; nt < 8; nt++) {
      const int row = m0 + wm + mt * 16 + gq;
      const int col = n0 + wn + nt * 8 + 2 * t;
      const float b0v = bih[col], b1v = bih[col + 1];
      float* o = g_gi + (size_t)row * GG + col;
      o[0] = acc[mt][nt][0] + b0v;
      o[1] = acc[mt][nt][1] + b1v;
      o = g_gi + (size_t)(row + 8) * GG + col;
      o[0] = acc[mt][nt][2] + b0v;
      o[1] = acc[mt][nt][3] + b1v;
    }
  }
}

// =================== Phase 2: persistent recurrent kernel =================
// 128 CTAs = 2 independent groups x 64 CTAs. Group owns 32 batch rows; CTA
// owns 16 hidden units (48 gate columns). Per step each CTA streams only its
// group's 32x1024 h (64 KB fp16) and syncs only within its 64-CTA group.
#define UPC 16
#define NC 48              // 3 gates * 16 units
#define WP2 520            // half2 per W smem row
#define HP2 68             // half2 per h-chunk smem row
#define CHUNK2 64          // half2 per chunk per row (=128 h cols)
#define NCHUNK 8

__device__ __forceinline__ void group_barrier(int grp) {
  __syncthreads();
  if (threadIdx.x == 0) {
    __threadfence();
    volatile unsigned* genp = &g_gen[grp * 32];
    const unsigned old = *genp;
    const int leaf = (blockIdx.x & 63) >> 3;
    if (atomicAdd(&g_leaf[(grp * 8 + leaf) * 32], 1u) == 7u) {
      if (atomicAdd(&g_root[grp * 32], 1u) == 7u) {
        g_root[grp * 32] = 0;
#pragma unroll
        for (int i = 0; i < 8; i++) g_leaf[(grp * 8 + i) * 32] = 0;
        __threadfence();
        atomicExch((unsigned*)genp, old + 1u);
      }
    }
    while (*genp == old) {}
    __threadfence();
  }
  __syncthreads();
}

__global__ __launch_bounds__(256, 1) void gru_rec_kernel(
    const float* __restrict__ Whh, const float* __restrict__ bhh,
    const float* __restrict__ h0, float* __restrict__ out) {
  extern __shared__ unsigned sm[];
  unsigned* sW = sm;                                   // [NC][WP2] half2, k16-perm
  unsigned* sHb[3];
  sHb[0] = sW + NC * WP2;                              // [RPG][HP2] half2
  sHb[1] = sHb[0] + RPG * HP2;
  sHb[2] = sHb[1] + RPG * HP2;
  float* sGh = (float*)(sHb[2] + RPG * HP2);           // [4 kq][RPG][NC]
  float* sBias = sGh + 4 * RPG * NC;                   // [NC]
  float* sHp = sBias + NC;                             // [RPG*UPC] own fp32 h slice

  const int tid = threadIdx.x;
  const int grp = blockIdx.x >> 6;       // group 0/1
  const int cid = blockIdx.x & 63;       // CTA within group
  const int u0 = cid * UPC;
  const int b0 = grp * RPG;

  // Stage W_hh slice as half2, k16-permuted (48 rows x 1024)
  for (int i = tid; i < NC * (II / 4); i += 256) {
    const int rowl = i >> 8;
    const int c4 = (i & 255) * 4;
    const int gate = rowl / UPC, ul = rowl % UPC;
    const float4 v = *(const float4*)(Whh + (size_t)(gate * HH + u0 + ul) * HH + c4);
    unsigned* d = &sW[rowl * WP2];
    const int p = hperm(c4 >> 1);
    d[p] = packh2(v.x, v.y);
    d[p + 2] = packh2(v.z, v.w);
  }
  if (tid < NC) {
    const int gate = tid / UPC, ul = tid % UPC;
    sBias[tid] = bhh[gate * HH + u0 + ul];
  }
  // init h0: own 16 cols x 32 rows
#pragma unroll
  for (int it = 0; it < 2; it++) {
    const int idx = tid + it * 256;
    const int r = idx >> 4, j = idx & 15;
    const float v = h0[(b0 + r) * HH + u0 + j];
    sHp[idx] = v;
    if ((j & 1) == 0) {
      const float v1 = h0[(b0 + r) * HH + u0 + j + 1];
      const int jp = j >> 1;  // 0..7 within our one k16 block
      g_h2[grp][0][r * H2 + 8 * cid + ((jp & 3) * 2) + (jp >> 2)] = packh2(v, v1);
    }
  }
  group_barrier(grp);

  const int w = tid >> 5, lane = tid & 31;
  const int gq = lane >> 2, t = lane & 3;
  const int mt = (w & 1);   // M tile (16 of 32 batch rows)
  const int kq = (w >> 1);  // K quarter within a chunk (2 k16 blocks each)

  for (int s = 0; s < SS; s++) {
    const unsigned* cur = g_h2[grp][s & 1];
    unsigned* nxt = g_h2[grp][(s + 1) & 1];

    // issue chunks 0..2 (3-deep pipeline); 2 float4 per thread per chunk
#pragma unroll
    for (int c = 0; c < 3; c++) {
#pragma unroll
      for (int k = 0; k < 2; k++) {
        const int f = tid + k * 256;               // float4 index 0..511
        const int r = f >> 4, cu = (f & 15) * 4;   // row, half2 offset
        cp16(&sHb[c][r * HP2 + cu], cur + (size_t)r * H2 + c * CHUNK2 + cu);
      }
      cp_commit();
    }

    // prefetch gi for this step
    float gir[2], giz[2], gin[2];
    {
      const float* gb = g_gi + (size_t)s * BB * GG;
#pragma unroll
      for (int it = 0; it < 2; it++) {
        const int idx = tid + it * 256;
        const int r = idx >> 4, j = idx & 15;
        const float* p = gb + (size_t)(b0 + r) * GG + u0 + j;
        gir[it] = p[0];
        giz[it] = p[HH];
        gin[it] = p[2 * HH];
      }
    }

    float acc[6][4];
#pragma unroll
    for (int nt = 0; nt < 6; nt++)
#pragma unroll
      for (int i = 0; i < 4; i++) acc[nt][i] = 0.f;

    for (int kc = 0; kc < NCHUNK; kc++) {
      if (kc <= 5) cp_wait<2>();
      else if (kc == 6) cp_wait<1>();
      else cp_wait<0>();
      __syncthreads();
      const unsigned* sh = sHb[kc % 3];
#pragma unroll
      for (int ks = 0; ks < 2; ks++) {
        const int kk = kq * 2 + ks;                       // k16 block within chunk (0..7)
        const unsigned* ap = &sh[(mt * 16 + gq) * HP2 + kk * 8 + 2 * t];
        const uint2 alo = *(const uint2*)ap;              // a0, a2
        const uint2 ahi = *(const uint2*)(ap + 8 * HP2);  // a1, a3
        const int kg = (kc * 8 + kk) * 8 + 2 * t;
#pragma unroll
        for (int nt = 0; nt < 6; nt++) {
          const uint2 b = *(const uint2*)&sW[(nt * 8 + gq) * WP2 + kg];
          mma16(acc[nt], alo.x, ahi.x, alo.y, ahi.y, b.x, b.y);
        }
      }
      __syncthreads();
      if (kc + 3 < NCHUNK) {
        unsigned* buf = sHb[kc % 3];
#pragma unroll
        for (int k = 0; k < 2; k++) {
          const int f = tid + k * 256;
          const int r = f >> 4, cu = (f & 15) * 4;
          cp16(&buf[r * HP2 + cu], cur + (size_t)r * H2 + (kc + 3) * CHUNK2 + cu);
        }
        cp_commit();
      }
    }

    // write K-quarter partials of gh
#pragma unroll
    for (int nt = 0; nt < 6; nt++) {
      const int col = nt * 8 + 2 * t;
      float* dst = &sGh[(kq * RPG + mt * 16 + gq) * NC + col];
      dst[0] = acc[nt][0];
      dst[1] = acc[nt][1];
      dst = &sGh[(kq * RPG + mt * 16 + 8 + gq) * NC + col];
      dst[0] = acc[nt][2];
      dst[1] = acc[nt][3];
    }
    __syncthreads();

    // pointwise GRU cell: this CTA's 16 units x 32 batch rows
#pragma unroll
    for (int it = 0; it < 2; it++) {
      const int idx = tid + it * 256;
      const int r = idx >> 4, j = idx & 15;
      const int b = b0 + r;
      const int u = u0 + j;
      float hr = sBias[j], hz = sBias[UPC + j], hn = sBias[2 * UPC + j];
#pragma unroll
      for (int q = 0; q < 4; q++) {
        const float* pr = &sGh[(q * RPG + r) * NC];
        hr += pr[j];
        hz += pr[UPC + j];
        hn += pr[2 * UPC + j];
      }
      const float hp = sHp[idx];
      const float rr = 1.f / (1.f + __expf(-(gir[it] + hr)));
      const float zz = 1.f / (1.f + __expf(-(giz[it] + hz)));
      const float nn = tanhf(gin[it] + rr * hn);
      const float hnew = nn + zz * (hp - nn);
      sHp[idx] = hnew;
      const float hi = __shfl_down_sync(0xffffffffu, hnew, 1);
      if ((j & 1) == 0) {
        const int jp = j >> 1;
        nxt[r * H2 + 8 * cid + ((jp & 3) * 2) + (jp >> 2)] = packh2(hnew, hi);
      }
      out[((size_t)s * BB + b) * HH + u] = hnew;
      if (s == SS - 1) out[(size_t)SS * BB * HH + (size_t)b * HH + u] = hnew;
    }
    group_barrier(grp);
  }
}

// =================== launch =================
extern "C" void kernel_launch(void* const* d_in, const int* in_sizes, int n_in,
                              void* d_out, int out_size) {
  const float* x   = (const float*)d_in[0];
  const float* h0  = (const float*)d_in[1];
  const float* wih = (const float*)d_in[2];
  const float* whh = (const float*)d_in[3];
  const float* bih = (const float*)d_in[4];
  const float* bhh = (const float*)d_in[5];
  float* out = (float*)d_out;

  const int smem_rec =
      (NC * WP2 + 3 * RPG * HP2 + 4 * RPG * NC + NC + RPG * UPC) * 4;  // 152,768 B
  cudaFuncSetAttribute(gru_rec_kernel, cudaFuncAttributeMaxDynamicSharedMemorySize, smem_rec);

  gemm_gi_kernel<<<dim3(GG / BN, (SS * BB) / BM), 256>>>(x, wih, bih);
  gru_rec_kernel<<<GRP * CPG, 256, smem_rec>>>(whh, bhh, h0, out);
}